// round 1
// baseline (speedup 1.0000x reference)
#include <cuda_runtime.h>
#include <cstddef>

// Problem constants
#define Bc 4
#define Sc 1024
#define Dc 1024
#define Hc 16
#define DKc 64
#define DVc 64
#define Mc (Bc * Sc)        // 4096 rows for the big GEMMs
#define HDc (Hc * DKc)      // 1024

// Static device scratch (allocation-free rule: __device__ globals)
__device__ float g_Qp[Bc * Hc * Sc * DKc];   // [B,H,S,DK]
__device__ float g_Kp[Bc * Hc * Sc * DKc];
__device__ float g_Vp[Bc * Hc * Sc * DVc];
__device__ float g_ctx[Mc * HDc];            // concat layout [B,S,H*DV]
__device__ float g_obuf[Mc * Dc];            // pre-LN output
__device__ float g_attn_fb[(size_t)Bc * Hc * Sc * Sc]; // fallback attention buffer
__device__ int   g_mask_mode;                // 0=int32, 1=bytes(bool), 2=float32

// ---------------------------------------------------------------------------
// Mask dtype detection: deterministic, reads first 4KB only (safe for any of
// the candidate layouts since the mask buffer is >= 4 MB).
// ---------------------------------------------------------------------------
__global__ void detect_mask_kernel(const unsigned int* __restrict__ m) {
    bool allint = true, allfloat = true;
    for (int i = 0; i < 1024; i++) {
        unsigned int w = m[i];
        if (w > 1u) allint = false;
        if (w != 0u && w != 0x3F800000u) allfloat = false;
    }
    g_mask_mode = allint ? 0 : (allfloat ? 2 : 1);
}

// ---------------------------------------------------------------------------
// Tiled GEMM + bias: C = A[M,K] @ W[K,N] + bias[N]
// 64x64 block tile, 16x16 threads, 4x4 per-thread micro-tile, K-tile 16.
// TRANSOUT=1 writes to [B,H,S,DK] layout (for Q/K/V projections).
// ---------------------------------------------------------------------------
template <int TRANSOUT>
__global__ __launch_bounds__(256)
void gemm_bias_kernel(const float* __restrict__ A, const float* __restrict__ W,
                      const float* __restrict__ bias, float* __restrict__ C,
                      int M, int K, int N) {
    __shared__ float As[16][65];   // [k][row]
    __shared__ float Ws[16][65];   // [k][col]
    const int tx = threadIdx.x, ty = threadIdx.y;
    const int tid = ty * 16 + tx;
    const int row0 = blockIdx.y * 64;
    const int col0 = blockIdx.x * 64;

    float acc[4][4] = {};
    for (int kt = 0; kt < K; kt += 16) {
        for (int i = tid; i < 64 * 16; i += 256) {
            int r = i >> 4, c = i & 15;
            As[c][r] = A[(size_t)(row0 + r) * K + kt + c];
        }
        for (int i = tid; i < 16 * 64; i += 256) {
            int r = i >> 6, c = i & 63;
            Ws[r][c] = W[(size_t)(kt + r) * N + col0 + c];
        }
        __syncthreads();
#pragma unroll
        for (int kk = 0; kk < 16; kk++) {
            float a[4], w[4];
#pragma unroll
            for (int i = 0; i < 4; i++) a[i] = As[kk][ty * 4 + i];
#pragma unroll
            for (int j = 0; j < 4; j++) w[j] = Ws[kk][tx * 4 + j];
#pragma unroll
            for (int i = 0; i < 4; i++)
#pragma unroll
                for (int j = 0; j < 4; j++) acc[i][j] += a[i] * w[j];
        }
        __syncthreads();
    }

#pragma unroll
    for (int i = 0; i < 4; i++) {
#pragma unroll
        for (int j = 0; j < 4; j++) {
            int m = row0 + ty * 4 + i;
            int n = col0 + tx * 4 + j;
            float v = acc[i][j] + bias[n];
            if (TRANSOUT) {
                int b = m >> 10;          // m / Sc
                int s = m & 1023;         // m % Sc
                int h = n >> 6;           // n / 64
                int d = n & 63;
                g_Qp[0];                  // (no-op, keeps template unified)
                C[((((size_t)b * Hc + h) * Sc) + s) * DKc + d] = v;
            } else {
                C[(size_t)m * N + n] = v;
            }
        }
    }
}

// ---------------------------------------------------------------------------
// Scores: for each (b,h): S[q,k] = (Q[q,:] . K[k,:]) / 8, masked -> -1e9
// One block computes a 64x64 tile of one batch-head.
// ---------------------------------------------------------------------------
__global__ __launch_bounds__(256)
void scores_kernel(const float* __restrict__ Qp, const float* __restrict__ Kp,
                   const void* __restrict__ mask, float* __restrict__ attn) {
    const int z = blockIdx.z;            // b*H + h
    const int b = z >> 4;                // z / Hc
    const int q0 = blockIdx.y * 64;
    const int k0 = blockIdx.x * 64;
    __shared__ float Qs[64][65];
    __shared__ float Ks[64][65];
    const int tx = threadIdx.x, ty = threadIdx.y;
    const int tid = ty * 16 + tx;

    const float* Qb = Qp + (size_t)z * Sc * DKc;
    const float* Kb = Kp + (size_t)z * Sc * DKc;
    for (int i = tid; i < 64 * 64; i += 256) {
        int r = i >> 6, c = i & 63;
        Qs[r][c] = Qb[(size_t)(q0 + r) * DKc + c];
        Ks[r][c] = Kb[(size_t)(k0 + r) * DKc + c];
    }
    __syncthreads();

    float acc[4][4] = {};
#pragma unroll 4
    for (int k = 0; k < 64; k++) {
        float a[4], kk[4];
#pragma unroll
        for (int i = 0; i < 4; i++) a[i] = Qs[ty * 4 + i][k];
#pragma unroll
        for (int j = 0; j < 4; j++) kk[j] = Ks[tx * 4 + j][k];
#pragma unroll
        for (int i = 0; i < 4; i++)
#pragma unroll
            for (int j = 0; j < 4; j++) acc[i][j] += a[i] * kk[j];
    }

    const float scale = 0.125f;  // 1/sqrt(64)
    const int mode = g_mask_mode;
    const int* mi = (const int*)mask;
    const unsigned char* mb = (const unsigned char*)mask;
    const float* mf = (const float*)mask;

#pragma unroll
    for (int i = 0; i < 4; i++) {
#pragma unroll
        for (int j = 0; j < 4; j++) {
            int q = q0 + ty * 4 + i;
            int k = k0 + tx * 4 + j;
            size_t midx = (size_t)b * Sc * Sc + (size_t)q * Sc + k;
            bool masked;
            if (mode == 0)      masked = (mi[midx] != 0);
            else if (mode == 2) masked = (mf[midx] != 0.0f);
            else                masked = (mb[midx] != 0);
            float v = masked ? -1e9f : acc[i][j] * scale;
            attn[((size_t)z * Sc + q) * Sc + k] = v;
        }
    }
}

// ---------------------------------------------------------------------------
// Row softmax over the last dim (length 1024), in place. One block per row.
// ---------------------------------------------------------------------------
__global__ __launch_bounds__(256)
void softmax_kernel(float* __restrict__ attn) {
    const size_t row = blockIdx.x;
    float* p = attn + row * Sc;
    const int tid = threadIdx.x;
    __shared__ float red[256];

    float v[4];
    float mx = -3.0e38f;
#pragma unroll
    for (int j = 0; j < 4; j++) {
        v[j] = p[tid + j * 256];
        mx = fmaxf(mx, v[j]);
    }
    red[tid] = mx;
    __syncthreads();
    for (int s = 128; s > 0; s >>= 1) {
        if (tid < s) red[tid] = fmaxf(red[tid], red[tid + s]);
        __syncthreads();
    }
    mx = red[0];
    __syncthreads();

    float sum = 0.0f;
#pragma unroll
    for (int j = 0; j < 4; j++) {
        v[j] = expf(v[j] - mx);
        sum += v[j];
    }
    red[tid] = sum;
    __syncthreads();
    for (int s = 128; s > 0; s >>= 1) {
        if (tid < s) red[tid] += red[tid + s];
        __syncthreads();
    }
    float inv = 1.0f / red[0];
#pragma unroll
    for (int j = 0; j < 4; j++) p[tid + j * 256] = v[j] * inv;
}

// ---------------------------------------------------------------------------
// Context: for each (b,h): ctx = attn[S,S] @ V[S,64]; written to concat
// layout [B, S, H*DV]. One block = 64 q-rows x 64 dv-cols of one batch-head.
// ---------------------------------------------------------------------------
__global__ __launch_bounds__(256)
void context_kernel(const float* __restrict__ attn, const float* __restrict__ Vp,
                    float* __restrict__ ctx) {
    const int z = blockIdx.y;           // b*H + h
    const int b = z >> 4;
    const int h = z & 15;
    const int q0 = blockIdx.x * 64;
    __shared__ float As[16][65];        // [k][qrow]
    __shared__ float Vs[16][65];        // [k][dv]
    const int tx = threadIdx.x, ty = threadIdx.y;
    const int tid = ty * 16 + tx;

    const float* Ab = attn + (size_t)z * Sc * Sc;
    const float* Vb = Vp + (size_t)z * Sc * DVc;

    float acc[4][4] = {};
    for (int kt = 0; kt < Sc; kt += 16) {
        for (int i = tid; i < 64 * 16; i += 256) {
            int r = i >> 4, c = i & 15;
            As[c][r] = Ab[(size_t)(q0 + r) * Sc + kt + c];
        }
        for (int i = tid; i < 16 * 64; i += 256) {
            int r = i >> 6, c = i & 63;
            Vs[r][c] = Vb[(size_t)(kt + r) * DVc + c];
        }
        __syncthreads();
#pragma unroll
        for (int kk = 0; kk < 16; kk++) {
            float a[4], vv[4];
#pragma unroll
            for (int i = 0; i < 4; i++) a[i] = As[kk][ty * 4 + i];
#pragma unroll
            for (int j = 0; j < 4; j++) vv[j] = Vs[kk][tx * 4 + j];
#pragma unroll
            for (int i = 0; i < 4; i++)
#pragma unroll
                for (int j = 0; j < 4; j++) acc[i][j] += a[i] * vv[j];
        }
        __syncthreads();
    }

#pragma unroll
    for (int i = 0; i < 4; i++) {
#pragma unroll
        for (int j = 0; j < 4; j++) {
            int q = q0 + ty * 4 + i;
            int dv = tx * 4 + j;
            ctx[((size_t)b * Sc + q) * HDc + h * DVc + dv] = acc[i][j];
        }
    }
}

// ---------------------------------------------------------------------------
// Fused residual add + LayerNorm (weight=1, bias=0, eps=1e-5). One block/row.
// ---------------------------------------------------------------------------
__global__ __launch_bounds__(256)
void layernorm_kernel(const float* __restrict__ x, const float* __restrict__ resid,
                      float* __restrict__ out) {
    const size_t row = blockIdx.x;
    const float* xr = x + row * Dc;
    const float* rr = resid + row * Dc;
    float* orow = out + row * Dc;
    const int tid = threadIdx.x;
    __shared__ float red[256];

    float v[4];
    float s = 0.0f;
#pragma unroll
    for (int j = 0; j < 4; j++) {
        v[j] = xr[tid + j * 256] + rr[tid + j * 256];
        s += v[j];
    }
    red[tid] = s;
    __syncthreads();
    for (int t = 128; t > 0; t >>= 1) {
        if (tid < t) red[tid] += red[tid + t];
        __syncthreads();
    }
    float mean = red[0] * (1.0f / 1024.0f);
    __syncthreads();

    float vs = 0.0f;
#pragma unroll
    for (int j = 0; j < 4; j++) {
        float d = v[j] - mean;
        vs += d * d;
    }
    red[tid] = vs;
    __syncthreads();
    for (int t = 128; t > 0; t >>= 1) {
        if (tid < t) red[tid] += red[tid + t];
        __syncthreads();
    }
    float inv = rsqrtf(red[0] * (1.0f / 1024.0f) + 1e-5f);
#pragma unroll
    for (int j = 0; j < 4; j++) orow[tid + j * 256] = (v[j] - mean) * inv;
}

// ---------------------------------------------------------------------------
// Launch
// ---------------------------------------------------------------------------
extern "C" void kernel_launch(void* const* d_in, const int* in_sizes, int n_in,
                              void* d_out, int out_size) {
    const float* q    = (const float*)d_in[0];
    const float* k    = (const float*)d_in[1];
    const float* v    = (const float*)d_in[2];
    const void*  mask = d_in[3];
    const float* Wq   = (const float*)d_in[4];
    const float* bq   = (const float*)d_in[5];
    const float* Wk   = (const float*)d_in[6];
    const float* bk   = (const float*)d_in[7];
    const float* Wv   = (const float*)d_in[8];
    const float* bv   = (const float*)d_in[9];
    const float* Wo   = (const float*)d_in[10];
    const float* bo   = (const float*)d_in[11];
    float* out = (float*)d_out;

    // Scratch pointers (static __device__ arrays; no allocation)
    float *Qp, *Kp, *Vp, *ctx, *obuf, *attn_fb;
    cudaGetSymbolAddress((void**)&Qp, g_Qp);
    cudaGetSymbolAddress((void**)&Kp, g_Kp);
    cudaGetSymbolAddress((void**)&Vp, g_Vp);
    cudaGetSymbolAddress((void**)&ctx, g_ctx);
    cudaGetSymbolAddress((void**)&obuf, g_obuf);
    cudaGetSymbolAddress((void**)&attn_fb, g_attn_fb);

    const long long LN_ELEMS = (long long)Mc * Dc;                     // 4,194,304
    const long long ATTN_ELEMS = (long long)Bc * Hc * Sc * Sc;         // 67,108,864
    float* attn = ((long long)out_size >= LN_ELEMS + ATTN_ELEMS)
                      ? (out + (size_t)LN_ELEMS)
                      : attn_fb;

    detect_mask_kernel<<<1, 1>>>((const unsigned int*)mask);

    dim3 blk(16, 16);
    // Q/K/V projections: [4096,1024] @ [1024,1024] + bias -> [B,H,S,64]
    gemm_bias_kernel<1><<<dim3(16, 64), blk>>>(q, Wq, bq, Qp, Mc, Dc, HDc);
    gemm_bias_kernel<1><<<dim3(16, 64), blk>>>(k, Wk, bk, Kp, Mc, Dc, HDc);
    gemm_bias_kernel<1><<<dim3(16, 64), blk>>>(v, Wv, bv, Vp, Mc, Dc, HDc);

    // Masked scores -> attn buffer (raw, pre-softmax)
    scores_kernel<<<dim3(16, 16, Bc * Hc), blk>>>(Qp, Kp, mask, attn);

    // Row softmax in place
    softmax_kernel<<<Bc * Hc * Sc, 256>>>(attn);

    // Context GEMM -> concat layout
    context_kernel<<<dim3(16, Bc * Hc), blk>>>(attn, Vp, ctx);

    // Output projection
    gemm_bias_kernel<0><<<dim3(16, 64), blk>>>(ctx, Wo, bo, obuf, Mc, HDc, Dc);

    // Residual + LayerNorm -> first output
    layernorm_kernel<<<Mc, 256>>>(obuf, q, out);
}

// round 2
// speedup vs baseline: 1.7523x; 1.7523x over previous
#include <cuda_runtime.h>
#include <mma.h>
#include <cstddef>

using namespace nvcuda;

// Problem constants
#define Bc 4
#define Sc 1024
#define Dc 1024
#define Hc 16
#define DKc 64
#define DVc 64
#define Mc (Bc * Sc)        // 4096
#define HDc (Hc * DKc)      // 1024

// Static device scratch
__device__ float g_Qp[Bc * Hc * Sc * DKc];   // [B,H,S,DK]
__device__ float g_Kp[Bc * Hc * Sc * DKc];
__device__ float g_Vp[Bc * Hc * Sc * DVc];
__device__ float g_ctx[Mc * HDc];            // [B,S,H*DV]
__device__ float g_obuf[Mc * Dc];
__device__ float g_attn_fb[(size_t)Bc * Hc * Sc * Sc];
__device__ int   g_mask_mode;

__device__ __forceinline__ float to_tf32(float x) {
    float r;
    asm("cvt.rna.tf32.f32 %0, %1;" : "=f"(r) : "f"(x));
    return r;
}

using frag_a  = wmma::fragment<wmma::matrix_a, 16, 16, 8, wmma::precision::tf32, wmma::row_major>;
using frag_b  = wmma::fragment<wmma::matrix_b, 16, 16, 8, wmma::precision::tf32, wmma::row_major>;
using frag_bc = wmma::fragment<wmma::matrix_b, 16, 16, 8, wmma::precision::tf32, wmma::col_major>;
using frag_c  = wmma::fragment<wmma::accumulator, 16, 16, 8, float>;

// ---------------------------------------------------------------------------
// Mask dtype detection
// ---------------------------------------------------------------------------
__global__ void detect_mask_kernel(const unsigned int* __restrict__ m) {
    bool allint = true, allfloat = true;
    for (int i = 0; i < 1024; i++) {
        unsigned int w = m[i];
        if (w > 1u) allint = false;
        if (w != 0u && w != 0x3F800000u) allfloat = false;
    }
    g_mask_mode = allint ? 0 : (allfloat ? 2 : 1);
}

// ---------------------------------------------------------------------------
// TF32 tensor-core GEMM: C = A[M,K] @ W[K,N] (+bias)
// BM=128, BN=64, BK=16, 8 warps (4x2), warp tile 32x32 (2x2 wmma tiles).
// SPLIT=1: hi/lo split-TF32 (3 MMAs) for ~fp32 accuracy.
// MODE 0: plain row-major C (+bias)
// MODE 1: projection output to [B,H,S,64] (+bias)
// MODE 2: per-z batched (context GEMM), A=attn[z], B=V[z], out to concat layout
// ---------------------------------------------------------------------------
template <int SPLIT, int MODE>
__global__ __launch_bounds__(256)
void gemm_tc(const float* __restrict__ A, const float* __restrict__ W,
             const float* __restrict__ bias, float* __restrict__ C,
             int M, int K, int N) {
    constexpr int BM = 128, BN = 64, BK = 16;
    __shared__ float As[BM][BK + 4];
    __shared__ float Bs[BK][BN + 4];
    __shared__ float BiasS[16][BN + 4];

    const int tid = threadIdx.x;
    const int w = tid >> 5;
    const int wm = w >> 1;      // 0..3
    const int wn = w & 1;       // 0..1

    int row0, col0, z = 0;
    const float *Ab, *Bb;
    if (MODE == 2) {
        z = blockIdx.y;
        row0 = blockIdx.x * BM;
        col0 = 0;
        Ab = A + (size_t)z * K * K;   // attn[z]: [1024,1024]
        Bb = W + (size_t)z * K * N;   // V[z]:    [1024,64]
    } else {
        row0 = blockIdx.y * BM;
        col0 = blockIdx.x * BN;
        Ab = A;
        Bb = W;
    }

    frag_c acc[2][2];
    if (MODE != 2) {
        for (int i = tid; i < 16 * BN; i += 256) {
            int r = i >> 6, c = i & 63;
            BiasS[r][c] = bias[col0 + c];
        }
        __syncthreads();
#pragma unroll
        for (int ti = 0; ti < 2; ti++)
#pragma unroll
            for (int tj = 0; tj < 2; tj++)
                wmma::load_matrix_sync(acc[ti][tj], &BiasS[0][wn * 32 + tj * 16],
                                       BN + 4, wmma::mem_row_major);
    } else {
#pragma unroll
        for (int ti = 0; ti < 2; ti++)
#pragma unroll
            for (int tj = 0; tj < 2; tj++)
                wmma::fill_fragment(acc[ti][tj], 0.0f);
    }

    for (int kt = 0; kt < K; kt += BK) {
        // A tile: 128x16 = 512 float4, 2 per thread
#pragma unroll
        for (int i = tid; i < BM * BK / 4; i += 256) {
            int r = i >> 2;
            int c = (i & 3) * 4;
            *(float4*)&As[r][c] = *(const float4*)&Ab[(size_t)(row0 + r) * K + kt + c];
        }
        // B tile: 16x64 = 256 float4, 1 per thread
        {
            int r = tid >> 4;
            int c = (tid & 15) * 4;
            *(float4*)&Bs[r][c] = *(const float4*)&Bb[(size_t)(kt + r) * N + col0 + c];
        }
        __syncthreads();

#pragma unroll
        for (int ks = 0; ks < 2; ks++) {
            const int kb = ks * 8;
            frag_a fa_hi[2], fa_lo[2];
            frag_b fb_hi[2], fb_lo[2];
#pragma unroll
            for (int ti = 0; ti < 2; ti++) {
                wmma::load_matrix_sync(fa_hi[ti], &As[wm * 32 + ti * 16][kb], BK + 4);
                if (SPLIT) {
#pragma unroll
                    for (int e = 0; e < fa_hi[ti].num_elements; e++) {
                        float v = fa_hi[ti].x[e];
                        float h = to_tf32(v);
                        fa_hi[ti].x[e] = h;
                        fa_lo[ti].x[e] = to_tf32(v - h);
                    }
                } else {
#pragma unroll
                    for (int e = 0; e < fa_hi[ti].num_elements; e++)
                        fa_hi[ti].x[e] = to_tf32(fa_hi[ti].x[e]);
                }
            }
#pragma unroll
            for (int tj = 0; tj < 2; tj++) {
                wmma::load_matrix_sync(fb_hi[tj], &Bs[kb][wn * 32 + tj * 16], BN + 4);
                if (SPLIT) {
#pragma unroll
                    for (int e = 0; e < fb_hi[tj].num_elements; e++) {
                        float v = fb_hi[tj].x[e];
                        float h = to_tf32(v);
                        fb_hi[tj].x[e] = h;
                        fb_lo[tj].x[e] = to_tf32(v - h);
                    }
                } else {
#pragma unroll
                    for (int e = 0; e < fb_hi[tj].num_elements; e++)
                        fb_hi[tj].x[e] = to_tf32(fb_hi[tj].x[e]);
                }
            }
#pragma unroll
            for (int ti = 0; ti < 2; ti++)
#pragma unroll
                for (int tj = 0; tj < 2; tj++) {
                    wmma::mma_sync(acc[ti][tj], fa_hi[ti], fb_hi[tj], acc[ti][tj]);
                    if (SPLIT) {
                        wmma::mma_sync(acc[ti][tj], fa_hi[ti], fb_lo[tj], acc[ti][tj]);
                        wmma::mma_sync(acc[ti][tj], fa_lo[ti], fb_hi[tj], acc[ti][tj]);
                    }
                }
        }
        __syncthreads();
    }

#pragma unroll
    for (int ti = 0; ti < 2; ti++)
#pragma unroll
        for (int tj = 0; tj < 2; tj++) {
            int m0 = row0 + wm * 32 + ti * 16;
            int n0 = col0 + wn * 32 + tj * 16;
            float* Cp;
            int ld;
            if (MODE == 0) {
                Cp = C + (size_t)m0 * N + n0;
                ld = N;
            } else if (MODE == 1) {
                int b = m0 >> 10, s = m0 & 1023, h = n0 >> 6, d = n0 & 63;
                Cp = C + ((size_t)(b * Hc + h) * Sc + s) * 64 + d;
                ld = 64;
            } else {
                int b = z >> 4, h = z & 15;
                Cp = C + ((size_t)(b * Sc + m0) * HDc) + h * DVc + n0;
                ld = HDc;
            }
            wmma::store_matrix_sync(Cp, acc[ti][tj], ld, wmma::mem_row_major);
        }
}

// ---------------------------------------------------------------------------
// Scores: S[q,k'] = (Q[q,:] . K[k',:]) / 8, masked -> -1e9.  Split-TF32.
// Block: 64x64 tile of one (b,h). 8 warps (2x4), warp tile 32x16.
// ---------------------------------------------------------------------------
__global__ __launch_bounds__(256)
void scores_tc(const float* __restrict__ Qp, const float* __restrict__ Kp,
               const void* __restrict__ mask, float* __restrict__ attn) {
    __shared__ float Qs[64][68];
    __shared__ float Ks[64][68];

    const int z = blockIdx.z;
    const int b = z >> 4;
    const int q0 = blockIdx.y * 64;
    const int k0 = blockIdx.x * 64;
    const int tid = threadIdx.x;
    const int w = tid >> 5;
    const int wm = w & 1;       // 0..1 : 32-row half
    const int wn = w >> 1;      // 0..3 : 16-col strip

    const float* Qb = Qp + (size_t)z * Sc * DKc;
    const float* Kb = Kp + (size_t)z * Sc * DKc;

#pragma unroll
    for (int i = tid; i < 1024; i += 256) {
        int r = i >> 4, c = (i & 15) * 4;
        *(float4*)&Qs[r][c] = *(const float4*)&Qb[(size_t)(q0 + r) * 64 + c];
        *(float4*)&Ks[r][c] = *(const float4*)&Kb[(size_t)(k0 + r) * 64 + c];
    }
    __syncthreads();

    frag_c acc[2];
    wmma::fill_fragment(acc[0], 0.0f);
    wmma::fill_fragment(acc[1], 0.0f);

#pragma unroll
    for (int ks = 0; ks < 8; ks++) {
        const int kb = ks * 8;
        frag_a fa_hi[2], fa_lo[2];
#pragma unroll
        for (int ti = 0; ti < 2; ti++) {
            wmma::load_matrix_sync(fa_hi[ti], &Qs[wm * 32 + ti * 16][kb], 68);
#pragma unroll
            for (int e = 0; e < fa_hi[ti].num_elements; e++) {
                float v = fa_hi[ti].x[e];
                float h = to_tf32(v);
                fa_hi[ti].x[e] = h;
                fa_lo[ti].x[e] = to_tf32(v - h);
            }
        }
        frag_bc fb_hi, fb_lo;
        wmma::load_matrix_sync(fb_hi, &Ks[wn * 16][kb], 68);
#pragma unroll
        for (int e = 0; e < fb_hi.num_elements; e++) {
            float v = fb_hi.x[e];
            float h = to_tf32(v);
            fb_hi.x[e] = h;
            fb_lo.x[e] = to_tf32(v - h);
        }
#pragma unroll
        for (int ti = 0; ti < 2; ti++) {
            wmma::mma_sync(acc[ti], fa_hi[ti], fb_hi, acc[ti]);
            wmma::mma_sync(acc[ti], fa_hi[ti], fb_lo, acc[ti]);
            wmma::mma_sync(acc[ti], fa_lo[ti], fb_hi, acc[ti]);
        }
    }
    __syncthreads();   // all reads of Qs done; reuse as staging
#pragma unroll
    for (int ti = 0; ti < 2; ti++)
        wmma::store_matrix_sync(&Qs[wm * 32 + ti * 16][wn * 16], acc[ti], 68,
                                wmma::mem_row_major);
    __syncthreads();

    const int mode = g_mask_mode;
    const int* mi = (const int*)mask;
    const unsigned char* mb = (const unsigned char*)mask;
    const float* mf = (const float*)mask;

#pragma unroll
    for (int i = tid; i < 4096; i += 256) {
        int r = i >> 6, c = i & 63;
        int q = q0 + r, k = k0 + c;
        size_t midx = (size_t)b * Sc * Sc + (size_t)q * Sc + k;
        bool masked;
        if (mode == 0)      masked = (mi[midx] != 0);
        else if (mode == 2) masked = (mf[midx] != 0.0f);
        else                masked = (mb[midx] != 0);
        float v = masked ? -1e9f : Qs[r][c] * 0.125f;
        attn[((size_t)z * Sc + q) * Sc + k] = v;
    }
}

// ---------------------------------------------------------------------------
// Row softmax (length 1024), in place.
// ---------------------------------------------------------------------------
__global__ __launch_bounds__(256)
void softmax_kernel(float* __restrict__ attn) {
    const size_t row = blockIdx.x;
    float* p = attn + row * Sc;
    const int tid = threadIdx.x;
    __shared__ float red[256];

    float v[4];
    float mx = -3.0e38f;
#pragma unroll
    for (int j = 0; j < 4; j++) {
        v[j] = p[tid + j * 256];
        mx = fmaxf(mx, v[j]);
    }
    red[tid] = mx;
    __syncthreads();
    for (int s = 128; s > 0; s >>= 1) {
        if (tid < s) red[tid] = fmaxf(red[tid], red[tid + s]);
        __syncthreads();
    }
    mx = red[0];
    __syncthreads();

    float sum = 0.0f;
#pragma unroll
    for (int j = 0; j < 4; j++) {
        v[j] = expf(v[j] - mx);
        sum += v[j];
    }
    red[tid] = sum;
    __syncthreads();
    for (int s = 128; s > 0; s >>= 1) {
        if (tid < s) red[tid] += red[tid + s];
        __syncthreads();
    }
    float inv = 1.0f / red[0];
#pragma unroll
    for (int j = 0; j < 4; j++) p[tid + j * 256] = v[j] * inv;
}

// ---------------------------------------------------------------------------
// Fused residual add + LayerNorm
// ---------------------------------------------------------------------------
__global__ __launch_bounds__(256)
void layernorm_kernel(const float* __restrict__ x, const float* __restrict__ resid,
                      float* __restrict__ out) {
    const size_t row = blockIdx.x;
    const float* xr = x + row * Dc;
    const float* rr = resid + row * Dc;
    float* orow = out + row * Dc;
    const int tid = threadIdx.x;
    __shared__ float red[256];

    float v[4];
    float s = 0.0f;
#pragma unroll
    for (int j = 0; j < 4; j++) {
        v[j] = xr[tid + j * 256] + rr[tid + j * 256];
        s += v[j];
    }
    red[tid] = s;
    __syncthreads();
    for (int t = 128; t > 0; t >>= 1) {
        if (tid < t) red[tid] += red[tid + t];
        __syncthreads();
    }
    float mean = red[0] * (1.0f / 1024.0f);
    __syncthreads();

    float vs = 0.0f;
#pragma unroll
    for (int j = 0; j < 4; j++) {
        float d = v[j] - mean;
        vs += d * d;
    }
    red[tid] = vs;
    __syncthreads();
    for (int t = 128; t > 0; t >>= 1) {
        if (tid < t) red[tid] += red[tid + t];
        __syncthreads();
    }
    float inv = rsqrtf(red[0] * (1.0f / 1024.0f) + 1e-5f);
#pragma unroll
    for (int j = 0; j < 4; j++) orow[tid + j * 256] = (v[j] - mean) * inv;
}

// ---------------------------------------------------------------------------
// Launch
// ---------------------------------------------------------------------------
extern "C" void kernel_launch(void* const* d_in, const int* in_sizes, int n_in,
                              void* d_out, int out_size) {
    const float* q    = (const float*)d_in[0];
    const float* k    = (const float*)d_in[1];
    const float* v    = (const float*)d_in[2];
    const void*  mask = d_in[3];
    const float* Wq   = (const float*)d_in[4];
    const float* bq   = (const float*)d_in[5];
    const float* Wk   = (const float*)d_in[6];
    const float* bk   = (const float*)d_in[7];
    const float* Wv   = (const float*)d_in[8];
    const float* bv   = (const float*)d_in[9];
    const float* Wo   = (const float*)d_in[10];
    const float* bo   = (const float*)d_in[11];
    float* out = (float*)d_out;

    float *Qp, *Kp, *Vp, *ctx, *obuf, *attn_fb;
    cudaGetSymbolAddress((void**)&Qp, g_Qp);
    cudaGetSymbolAddress((void**)&Kp, g_Kp);
    cudaGetSymbolAddress((void**)&Vp, g_Vp);
    cudaGetSymbolAddress((void**)&ctx, g_ctx);
    cudaGetSymbolAddress((void**)&obuf, g_obuf);
    cudaGetSymbolAddress((void**)&attn_fb, g_attn_fb);

    const long long LN_ELEMS = (long long)Mc * Dc;
    const long long ATTN_ELEMS = (long long)Bc * Hc * Sc * Sc;
    float* attn = ((long long)out_size >= LN_ELEMS + ATTN_ELEMS)
                      ? (out + (size_t)LN_ELEMS)
                      : attn_fb;

    detect_mask_kernel<<<1, 1>>>((const unsigned int*)mask);

    // Q/K projections: split-TF32 (feeds the error-sensitive softmax path)
    gemm_tc<1, 1><<<dim3(16, 32), 256>>>(q, Wq, bq, Qp, Mc, Dc, HDc);
    gemm_tc<1, 1><<<dim3(16, 32), 256>>>(k, Wk, bk, Kp, Mc, Dc, HDc);
    // V projection: single TF32
    gemm_tc<0, 1><<<dim3(16, 32), 256>>>(v, Wv, bv, Vp, Mc, Dc, HDc);

    // Scores (split-TF32) + mask
    scores_tc<<<dim3(16, 16, Bc * Hc), 256>>>(Qp, Kp, mask, attn);

    // Softmax in place
    softmax_kernel<<<Bc * Hc * Sc, 256>>>(attn);

    // Context GEMM (single TF32) -> concat layout
    gemm_tc<0, 2><<<dim3(8, 64), 256>>>(attn, Vp, nullptr, ctx, Sc, Sc, DVc);

    // Output projection (single TF32)
    gemm_tc<0, 0><<<dim3(16, 32), 256>>>(ctx, Wo, bo, obuf, Mc, HDc, Dc);

    // Residual + LayerNorm
    layernorm_kernel<<<Mc, 256>>>(obuf, q, out);
}

// round 3
// speedup vs baseline: 2.6467x; 1.5104x over previous
#include <cuda_runtime.h>
#include <cuda_bf16.h>
#include <mma.h>
#include <cstddef>

using namespace nvcuda;

// Problem constants
#define Bc 4
#define Sc 1024
#define Dc 1024
#define Hc 16
#define DKc 64
#define DVc 64
#define Mc (Bc * Sc)        // 4096
#define HDc (Hc * DKc)      // 1024

// Static device scratch
__device__ float g_Qp[Bc * Hc * Sc * DKc];   // [B,H,S,DK]
__device__ float g_Kp[Bc * Hc * Sc * DKc];
__device__ float g_Vp[Bc * Hc * Sc * DVc];
__device__ float g_ctx[Mc * HDc];            // [B,S,H*DV]
__device__ float g_obuf[Mc * Dc];
__device__ float g_attn_fb[(size_t)Bc * Hc * Sc * Sc];
__device__ int   g_mask_mode;

__device__ __forceinline__ float to_tf32(float x) {
    float r;
    asm("cvt.rna.tf32.f32 %0, %1;" : "=f"(r) : "f"(x));
    return r;
}

// TF32 fragments (16x16x8)
using frag_a  = wmma::fragment<wmma::matrix_a, 16, 16, 8, wmma::precision::tf32, wmma::row_major>;
using frag_b  = wmma::fragment<wmma::matrix_b, 16, 16, 8, wmma::precision::tf32, wmma::row_major>;
using frag_c  = wmma::fragment<wmma::accumulator, 16, 16, 8, float>;

// bf16 fragments (16x16x16)
using bfrag_a  = wmma::fragment<wmma::matrix_a, 16, 16, 16, __nv_bfloat16, wmma::row_major>;
using bfrag_b  = wmma::fragment<wmma::matrix_b, 16, 16, 16, __nv_bfloat16, wmma::row_major>;
using bfrag_bc = wmma::fragment<wmma::matrix_b, 16, 16, 16, __nv_bfloat16, wmma::col_major>;
using bfrag_c  = wmma::fragment<wmma::accumulator, 16, 16, 16, float>;

__device__ __forceinline__ void cvt_store4(__nv_bfloat16* dh, __nv_bfloat16* dl, float4 v) {
    float a[4] = {v.x, v.y, v.z, v.w};
#pragma unroll
    for (int j = 0; j < 4; j++) {
        __nv_bfloat16 h = __float2bfloat16(a[j]);
        dh[j] = h;
        dl[j] = __float2bfloat16(a[j] - __bfloat162float(h));
    }
}

// ---------------------------------------------------------------------------
// Mask dtype detection
// ---------------------------------------------------------------------------
__global__ void detect_mask_kernel(const unsigned int* __restrict__ m) {
    bool allint = true, allfloat = true;
    for (int i = 0; i < 1024; i++) {
        unsigned int w = m[i];
        if (w > 1u) allint = false;
        if (w != 0u && w != 0x3F800000u) allfloat = false;
    }
    g_mask_mode = allint ? 0 : (allfloat ? 2 : 1);
}

// ---------------------------------------------------------------------------
// Split-bf16 projection GEMM: C[b,h,s,d] = A[4096,1024] @ W[1024,1024] + bias
// BM=128, BN=64 (one head per block-col), BK=16, double-buffered smem,
// register-staged LDG prefetch. 3-term hi/lo split for ~fp32 accuracy.
// ---------------------------------------------------------------------------
__global__ __launch_bounds__(256)
void proj_bf16_split(const float* __restrict__ A, const float* __restrict__ W,
                     const float* __restrict__ bias, float* __restrict__ C) {
    constexpr int LDA = 24;    // bf16 elems, 48B (multiple of 16B)
    constexpr int LDW = 72;    // bf16 elems, 144B
    constexpr int LDST = 68;   // fp32 staging ld

    __shared__ __align__(16) char buf[34816];
    __nv_bfloat16* Ahi = (__nv_bfloat16*)buf;        // [2][128][24]
    __nv_bfloat16* Alo = Ahi + 2 * 128 * LDA;
    __nv_bfloat16* Whi = Alo + 2 * 128 * LDA;        // [2][16][72]
    __nv_bfloat16* Wlo = Whi + 2 * 16 * LDW;
    float* stg = (float*)buf;                        // [128][68] epilogue reuse

    const int tid = threadIdx.x;
    const int w = tid >> 5;
    const int wm = w >> 1;      // 0..3 (32-row strip)
    const int wn = w & 1;       // 0..1 (32-col strip)
    const int row0 = blockIdx.y * 128;
    const int col0 = blockIdx.x * 64;

    const int ar = tid >> 2, ac = (tid & 3) * 4;     // A-tile load coords
    const int wr = tid >> 4, wc = (tid & 15) * 4;    // W-tile load coords

    bfrag_c acc[2][2];
#pragma unroll
    for (int ti = 0; ti < 2; ti++)
#pragma unroll
        for (int tj = 0; tj < 2; tj++) wmma::fill_fragment(acc[ti][tj], 0.0f);

    float4 ra0, ra1, rw;

    // prologue: load tile 0
    ra0 = *(const float4*)&A[(size_t)(row0 + ar) * Dc + ac];
    ra1 = *(const float4*)&A[(size_t)(row0 + ar + 64) * Dc + ac];
    rw  = *(const float4*)&W[(size_t)wr * HDc + col0 + wc];
    cvt_store4(Ahi + ar * LDA + ac, Alo + ar * LDA + ac, ra0);
    cvt_store4(Ahi + (ar + 64) * LDA + ac, Alo + (ar + 64) * LDA + ac, ra1);
    cvt_store4(Whi + wr * LDW + wc, Wlo + wr * LDW + wc, rw);
    __syncthreads();

    for (int kt = 0; kt < 64; kt++) {
        if (kt < 63) {
            int k = (kt + 1) * 16;
            ra0 = *(const float4*)&A[(size_t)(row0 + ar) * Dc + k + ac];
            ra1 = *(const float4*)&A[(size_t)(row0 + ar + 64) * Dc + k + ac];
            rw  = *(const float4*)&W[(size_t)(k + wr) * HDc + col0 + wc];
        }
        const int cur = kt & 1;
        const int cb = cur * 128 * LDA;
        const int wb = cur * 16 * LDW;

        bfrag_a fah[2], fal[2];
        bfrag_b fbh[2], fbl[2];
#pragma unroll
        for (int ti = 0; ti < 2; ti++) {
            wmma::load_matrix_sync(fah[ti], Ahi + cb + (wm * 32 + ti * 16) * LDA, LDA);
            wmma::load_matrix_sync(fal[ti], Alo + cb + (wm * 32 + ti * 16) * LDA, LDA);
        }
#pragma unroll
        for (int tj = 0; tj < 2; tj++) {
            wmma::load_matrix_sync(fbh[tj], Whi + wb + wn * 32 + tj * 16, LDW);
            wmma::load_matrix_sync(fbl[tj], Wlo + wb + wn * 32 + tj * 16, LDW);
        }
#pragma unroll
        for (int ti = 0; ti < 2; ti++)
#pragma unroll
            for (int tj = 0; tj < 2; tj++) {
                wmma::mma_sync(acc[ti][tj], fah[ti], fbh[tj], acc[ti][tj]);
                wmma::mma_sync(acc[ti][tj], fah[ti], fbl[tj], acc[ti][tj]);
                wmma::mma_sync(acc[ti][tj], fal[ti], fbh[tj], acc[ti][tj]);
            }

        if (kt < 63) {
            const int nb = (cur ^ 1) * 128 * LDA;
            const int nw = (cur ^ 1) * 16 * LDW;
            cvt_store4(Ahi + nb + ar * LDA + ac, Alo + nb + ar * LDA + ac, ra0);
            cvt_store4(Ahi + nb + (ar + 64) * LDA + ac, Alo + nb + (ar + 64) * LDA + ac, ra1);
            cvt_store4(Whi + nw + wr * LDW + wc, Wlo + nw + wr * LDW + wc, rw);
        }
        __syncthreads();
    }

    // epilogue: acc -> staging -> [B,H,S,64] (+bias)
#pragma unroll
    for (int ti = 0; ti < 2; ti++)
#pragma unroll
        for (int tj = 0; tj < 2; tj++)
            wmma::store_matrix_sync(&stg[(wm * 32 + ti * 16) * LDST + wn * 32 + tj * 16],
                                    acc[ti][tj], LDST, wmma::mem_row_major);
    __syncthreads();

    const int b = row0 >> 10;
    const int h = blockIdx.x;
    float4 bi = *(const float4*)&bias[col0 + ((tid & 15) * 4)];
#pragma unroll
    for (int i = tid; i < 2048; i += 256) {
        int r = i >> 4, c4 = (i & 15) * 4;
        int s = (row0 + r) & 1023;
        float4 v = *(float4*)&stg[r * LDST + c4];
        v.x += bi.x; v.y += bi.y; v.z += bi.z; v.w += bi.w;
        *(float4*)&C[(((size_t)b * Hc + h) * Sc + s) * 64 + c4] = v;
    }
}

// ---------------------------------------------------------------------------
// Split-bf16 scores: S[q,k'] = (Q[q,:].K[k',:]) / 8, masked -> -1e9
// 64x64 tile per block of one (b,h). 8 warps: wm in {0,1} (32 rows),
// wn in {0..3} (16 cols).
// ---------------------------------------------------------------------------
__global__ __launch_bounds__(256)
void scores_bf16(const float* __restrict__ Qp, const float* __restrict__ Kp,
                 const void* __restrict__ mask, float* __restrict__ attn) {
    constexpr int LDT = 72;    // bf16 tile ld (144B)
    constexpr int LDST = 68;   // fp32 staging ld

    __shared__ __align__(16) char buf[36864];
    __nv_bfloat16* Qhi = (__nv_bfloat16*)buf;        // [64][72]
    __nv_bfloat16* Qlo = Qhi + 64 * LDT;
    __nv_bfloat16* Khi = Qlo + 64 * LDT;
    __nv_bfloat16* Klo = Khi + 64 * LDT;
    float* stg = (float*)buf;                        // [64][68] epilogue reuse

    const int z = blockIdx.z;
    const int b = z >> 4;
    const int q0 = blockIdx.y * 64;
    const int k0 = blockIdx.x * 64;
    const int tid = threadIdx.x;
    const int w = tid >> 5;
    const int wm = w & 1;
    const int wn = w >> 1;

    const float* Qb = Qp + (size_t)z * Sc * DKc;
    const float* Kb = Kp + (size_t)z * Sc * DKc;

#pragma unroll
    for (int i = tid; i < 1024; i += 256) {
        int r = i >> 4, c = (i & 15) * 4;
        float4 q4 = *(const float4*)&Qb[(size_t)(q0 + r) * 64 + c];
        float4 k4 = *(const float4*)&Kb[(size_t)(k0 + r) * 64 + c];
        cvt_store4(Qhi + r * LDT + c, Qlo + r * LDT + c, q4);
        cvt_store4(Khi + r * LDT + c, Klo + r * LDT + c, k4);
    }
    __syncthreads();

    bfrag_c acc[2];
    wmma::fill_fragment(acc[0], 0.0f);
    wmma::fill_fragment(acc[1], 0.0f);

#pragma unroll
    for (int ks = 0; ks < 4; ks++) {
        const int kb = ks * 16;
        bfrag_a fah[2], fal[2];
#pragma unroll
        for (int ti = 0; ti < 2; ti++) {
            wmma::load_matrix_sync(fah[ti], Qhi + (wm * 32 + ti * 16) * LDT + kb, LDT);
            wmma::load_matrix_sync(fal[ti], Qlo + (wm * 32 + ti * 16) * LDT + kb, LDT);
        }
        bfrag_bc fbh, fbl;
        wmma::load_matrix_sync(fbh, Khi + (wn * 16) * LDT + kb, LDT);
        wmma::load_matrix_sync(fbl, Klo + (wn * 16) * LDT + kb, LDT);
#pragma unroll
        for (int ti = 0; ti < 2; ti++) {
            wmma::mma_sync(acc[ti], fah[ti], fbh, acc[ti]);
            wmma::mma_sync(acc[ti], fah[ti], fbl, acc[ti]);
            wmma::mma_sync(acc[ti], fal[ti], fbh, acc[ti]);
        }
    }
    __syncthreads();
#pragma unroll
    for (int ti = 0; ti < 2; ti++)
        wmma::store_matrix_sync(&stg[(wm * 32 + ti * 16) * LDST + wn * 16], acc[ti],
                                LDST, wmma::mem_row_major);
    __syncthreads();

    const int mode = g_mask_mode;
    const int* mi = (const int*)mask;
    const unsigned char* mb = (const unsigned char*)mask;
    const float* mf = (const float*)mask;

#pragma unroll
    for (int i = tid; i < 4096; i += 256) {
        int r = i >> 6, c = i & 63;
        int qq = q0 + r, kk = k0 + c;
        size_t midx = (size_t)b * Sc * Sc + (size_t)qq * Sc + kk;
        bool masked;
        if (mode == 0)      masked = (mi[midx] != 0);
        else if (mode == 2) masked = (mf[midx] != 0.0f);
        else                masked = (mb[midx] != 0);
        float v = masked ? -1e9f : stg[r * LDST + c] * 0.125f;
        attn[((size_t)z * Sc + qq) * Sc + kk] = v;
    }
}

// ---------------------------------------------------------------------------
// TF32 tensor-core GEMM (single precision term) for V-proj / context / outproj
// MODE 0: plain row-major C (+bias); MODE 1: [B,H,S,64] (+bias);
// MODE 2: batched context, out to concat layout.
// ---------------------------------------------------------------------------
template <int MODE>
__global__ __launch_bounds__(256)
void gemm_tc(const float* __restrict__ A, const float* __restrict__ W,
             const float* __restrict__ bias, float* __restrict__ C,
             int M, int K, int N) {
    constexpr int BM = 128, BN = 64, BK = 16;
    __shared__ float As[BM][BK + 4];
    __shared__ float Bs[BK][BN + 4];
    __shared__ float BiasS[16][BN + 4];

    const int tid = threadIdx.x;
    const int w = tid >> 5;
    const int wm = w >> 1;
    const int wn = w & 1;

    int row0, col0, z = 0;
    const float *Ab, *Bb;
    if (MODE == 2) {
        z = blockIdx.y;
        row0 = blockIdx.x * BM;
        col0 = 0;
        Ab = A + (size_t)z * K * K;
        Bb = W + (size_t)z * K * N;
    } else {
        row0 = blockIdx.y * BM;
        col0 = blockIdx.x * BN;
        Ab = A;
        Bb = W;
    }

    frag_c acc[2][2];
    if (MODE != 2) {
        for (int i = tid; i < 16 * BN; i += 256) {
            int r = i >> 6, c = i & 63;
            BiasS[r][c] = bias[col0 + c];
        }
        __syncthreads();
#pragma unroll
        for (int ti = 0; ti < 2; ti++)
#pragma unroll
            for (int tj = 0; tj < 2; tj++)
                wmma::load_matrix_sync(acc[ti][tj], &BiasS[0][wn * 32 + tj * 16],
                                       BN + 4, wmma::mem_row_major);
    } else {
#pragma unroll
        for (int ti = 0; ti < 2; ti++)
#pragma unroll
            for (int tj = 0; tj < 2; tj++)
                wmma::fill_fragment(acc[ti][tj], 0.0f);
    }

    for (int kt = 0; kt < K; kt += BK) {
#pragma unroll
        for (int i = tid; i < BM * BK / 4; i += 256) {
            int r = i >> 2;
            int c = (i & 3) * 4;
            *(float4*)&As[r][c] = *(const float4*)&Ab[(size_t)(row0 + r) * K + kt + c];
        }
        {
            int r = tid >> 4;
            int c = (tid & 15) * 4;
            *(float4*)&Bs[r][c] = *(const float4*)&Bb[(size_t)(kt + r) * N + col0 + c];
        }
        __syncthreads();

#pragma unroll
        for (int ks = 0; ks < 2; ks++) {
            const int kb = ks * 8;
            frag_a fa[2];
            frag_b fb[2];
#pragma unroll
            for (int ti = 0; ti < 2; ti++) {
                wmma::load_matrix_sync(fa[ti], &As[wm * 32 + ti * 16][kb], BK + 4);
#pragma unroll
                for (int e = 0; e < fa[ti].num_elements; e++)
                    fa[ti].x[e] = to_tf32(fa[ti].x[e]);
            }
#pragma unroll
            for (int tj = 0; tj < 2; tj++) {
                wmma::load_matrix_sync(fb[tj], &Bs[kb][wn * 32 + tj * 16], BN + 4);
#pragma unroll
                for (int e = 0; e < fb[tj].num_elements; e++)
                    fb[tj].x[e] = to_tf32(fb[tj].x[e]);
            }
#pragma unroll
            for (int ti = 0; ti < 2; ti++)
#pragma unroll
                for (int tj = 0; tj < 2; tj++)
                    wmma::mma_sync(acc[ti][tj], fa[ti], fb[tj], acc[ti][tj]);
        }
        __syncthreads();
    }

#pragma unroll
    for (int ti = 0; ti < 2; ti++)
#pragma unroll
        for (int tj = 0; tj < 2; tj++) {
            int m0 = row0 + wm * 32 + ti * 16;
            int n0 = col0 + wn * 32 + tj * 16;
            float* Cp;
            int ld;
            if (MODE == 0) {
                Cp = C + (size_t)m0 * N + n0;
                ld = N;
            } else if (MODE == 1) {
                int b = m0 >> 10, s = m0 & 1023, h = n0 >> 6, d = n0 & 63;
                Cp = C + ((size_t)(b * Hc + h) * Sc + s) * 64 + d;
                ld = 64;
            } else {
                int b = z >> 4, h = z & 15;
                Cp = C + ((size_t)(b * Sc + m0) * HDc) + h * DVc + n0;
                ld = HDc;
            }
            wmma::store_matrix_sync(Cp, acc[ti][tj], ld, wmma::mem_row_major);
        }
}

// ---------------------------------------------------------------------------
// Row softmax (length 1024), in place, vectorized + warp shuffles.
// ---------------------------------------------------------------------------
__global__ __launch_bounds__(256)
void softmax_kernel(float* __restrict__ attn) {
    const size_t row = blockIdx.x;
    float4* p = (float4*)(attn + row * Sc);
    const int tid = threadIdx.x;
    const int lane = tid & 31, wid = tid >> 5;
    __shared__ float sm[16];

    float4 v = p[tid];
    float mx = fmaxf(fmaxf(v.x, v.y), fmaxf(v.z, v.w));
#pragma unroll
    for (int o = 16; o; o >>= 1) mx = fmaxf(mx, __shfl_xor_sync(0xffffffffu, mx, o));
    if (lane == 0) sm[wid] = mx;
    __syncthreads();
    float m = sm[0];
#pragma unroll
    for (int i = 1; i < 8; i++) m = fmaxf(m, sm[i]);

    v.x = expf(v.x - m); v.y = expf(v.y - m);
    v.z = expf(v.z - m); v.w = expf(v.w - m);
    float s = (v.x + v.y) + (v.z + v.w);
#pragma unroll
    for (int o = 16; o; o >>= 1) s += __shfl_xor_sync(0xffffffffu, s, o);
    if (lane == 0) sm[8 + wid] = s;
    __syncthreads();
    float tot = 0.0f;
#pragma unroll
    for (int i = 0; i < 8; i++) tot += sm[8 + i];
    float inv = 1.0f / tot;
    v.x *= inv; v.y *= inv; v.z *= inv; v.w *= inv;
    p[tid] = v;
}

// ---------------------------------------------------------------------------
// Fused residual add + LayerNorm, vectorized.
// ---------------------------------------------------------------------------
__global__ __launch_bounds__(256)
void layernorm_kernel(const float* __restrict__ x, const float* __restrict__ resid,
                      float* __restrict__ out) {
    const size_t row = blockIdx.x;
    const float4* xr = (const float4*)(x + row * Dc);
    const float4* rr = (const float4*)(resid + row * Dc);
    float4* orow = (float4*)(out + row * Dc);
    const int tid = threadIdx.x;
    const int lane = tid & 31, wid = tid >> 5;
    __shared__ float sm[16];

    float4 a = xr[tid], b = rr[tid];
    float4 v = make_float4(a.x + b.x, a.y + b.y, a.z + b.z, a.w + b.w);
    float s = (v.x + v.y) + (v.z + v.w);
#pragma unroll
    for (int o = 16; o; o >>= 1) s += __shfl_xor_sync(0xffffffffu, s, o);
    if (lane == 0) sm[wid] = s;
    __syncthreads();
    float tot = 0.0f;
#pragma unroll
    for (int i = 0; i < 8; i++) tot += sm[i];
    float mean = tot * (1.0f / 1024.0f);

    float dx = v.x - mean, dy = v.y - mean, dz = v.z - mean, dw = v.w - mean;
    float vs = (dx * dx + dy * dy) + (dz * dz + dw * dw);
#pragma unroll
    for (int o = 16; o; o >>= 1) vs += __shfl_xor_sync(0xffffffffu, vs, o);
    if (lane == 0) sm[8 + wid] = vs;
    __syncthreads();
    float vtot = 0.0f;
#pragma unroll
    for (int i = 0; i < 8; i++) vtot += sm[8 + i];
    float inv = rsqrtf(vtot * (1.0f / 1024.0f) + 1e-5f);
    orow[tid] = make_float4(dx * inv, dy * inv, dz * inv, dw * inv);
}

// ---------------------------------------------------------------------------
// Launch
// ---------------------------------------------------------------------------
extern "C" void kernel_launch(void* const* d_in, const int* in_sizes, int n_in,
                              void* d_out, int out_size) {
    const float* q    = (const float*)d_in[0];
    const float* k    = (const float*)d_in[1];
    const float* v    = (const float*)d_in[2];
    const void*  mask = d_in[3];
    const float* Wq   = (const float*)d_in[4];
    const float* bq   = (const float*)d_in[5];
    const float* Wk   = (const float*)d_in[6];
    const float* bk   = (const float*)d_in[7];
    const float* Wv   = (const float*)d_in[8];
    const float* bv   = (const float*)d_in[9];
    const float* Wo   = (const float*)d_in[10];
    const float* bo   = (const float*)d_in[11];
    float* out = (float*)d_out;

    float *Qp, *Kp, *Vp, *ctx, *obuf, *attn_fb;
    cudaGetSymbolAddress((void**)&Qp, g_Qp);
    cudaGetSymbolAddress((void**)&Kp, g_Kp);
    cudaGetSymbolAddress((void**)&Vp, g_Vp);
    cudaGetSymbolAddress((void**)&ctx, g_ctx);
    cudaGetSymbolAddress((void**)&obuf, g_obuf);
    cudaGetSymbolAddress((void**)&attn_fb, g_attn_fb);

    const long long LN_ELEMS = (long long)Mc * Dc;
    const long long ATTN_ELEMS = (long long)Bc * Hc * Sc * Sc;
    float* attn = ((long long)out_size >= LN_ELEMS + ATTN_ELEMS)
                      ? (out + (size_t)LN_ELEMS)
                      : attn_fb;

    detect_mask_kernel<<<1, 1>>>((const unsigned int*)mask);

    // Q/K projections: split-bf16 (accuracy-critical path), pipelined
    proj_bf16_split<<<dim3(16, 32), 256>>>(q, Wq, bq, Qp);
    proj_bf16_split<<<dim3(16, 32), 256>>>(k, Wk, bk, Kp);
    // V projection: single TF32
    gemm_tc<1><<<dim3(16, 32), 256>>>(v, Wv, bv, Vp, Mc, Dc, HDc);

    // Scores (split-bf16) + mask
    scores_bf16<<<dim3(16, 16, Bc * Hc), 256>>>(Qp, Kp, mask, attn);

    // Softmax in place
    softmax_kernel<<<Bc * Hc * Sc, 256>>>(attn);

    // Context GEMM (single TF32) -> concat layout
    gemm_tc<2><<<dim3(8, 64), 256>>>(attn, Vp, nullptr, ctx, Sc, Sc, DVc);

    // Output projection (single TF32)
    gemm_tc<0><<<dim3(16, 32), 256>>>(ctx, Wo, bo, obuf, Mc, HDc, Dc);

    // Residual + LayerNorm
    layernorm_kernel<<<Mc, 256>>>(obuf, q, out);
}